// round 11
// baseline (speedup 1.0000x reference)
#include <cuda_runtime.h>
#include <cstdint>

// Problem constants
#define BSZ     8
#define KDIM    4096
#define NDIM    11008
#define RPW     4                        // rows per warp task
#define SPLITK  4
#define KCH     (KDIM / SPLITK)          // 1024 floats per K-chunk
#define KITERS  (KCH / 128)              // 8 iterations (128 floats/row/iter)
#define WARPS_PER_CTA 16
#define THREADS (WARPS_PER_CTA * 32)     // 512
#define NCTAS   148
#define TOTAL_WARPS (NCTAS * WARPS_PER_CTA)   // 2368
#define NROWGROUPS (NDIM / RPW)               // 2752
#define NTASKS  (NROWGROUPS * SPLITK)         // 11008
#define SMEM_BYTES (BSZ * KDIM * 4)           // 131072

// Split-K partial sums: [SPLITK][BSZ][NDIM]
__device__ float g_partial[SPLITK * BSZ * NDIM];
// per-rowgroup arrival counters (zero-init at load; restored to 0 each run)
__device__ int g_cnt[NROWGROUPS];

typedef unsigned long long ull;

// ---- packed f32x2 FMA (Blackwell f32x2 pipe) ----
__device__ __forceinline__ void ffma2(ull& d, ull a, ull b) {
    asm("fma.rn.f32x2 %0, %1, %2, %0;" : "+l"(d) : "l"(a), "l"(b));
}
__device__ __forceinline__ float sum2(ull a) {
    float lo, hi;
    asm("mov.b64 {%0, %1}, %2;" : "=f"(lo), "=f"(hi) : "l"(a));
    return lo + hi;
}
// streaming 128-bit global load as two packed f32x2 words (bypass L1 reuse)
__device__ __forceinline__ void ldg_cs_v2u64(const void* p, ull& a, ull& b) {
    asm("ld.global.cs.v2.u64 {%0, %1}, [%2];"
        : "=l"(a), "=l"(b) : "l"(p));
}
// L2-coherent scalar load (skip L1 for cross-SM-produced partials)
__device__ __forceinline__ float ldg_cg_f32(const float* p) {
    float v;
    asm volatile("ld.global.cg.f32 %0, [%1];" : "=f"(v) : "l"(p));
    return v;
}

extern __shared__ float xs[];   // [BSZ][KDIM] staged activations

__global__ __launch_bounds__(THREADS, 1)
void asl_gemv_kernel(const float* __restrict__ x,
                     const float* __restrict__ w,
                     float* __restrict__ out) {
    // ---- stage x into shared memory (131 KB), once per CTA ----
    {
        const float4* x4  = reinterpret_cast<const float4*>(x);
        float4*       xs4 = reinterpret_cast<float4*>(xs);
        #pragma unroll 8
        for (int i = threadIdx.x; i < BSZ * KDIM / 4; i += THREADS)
            xs4[i] = x4[i];
    }
    __syncthreads();

    const int lane  = threadIdx.x & 31;
    const int gwarp = blockIdx.x * WARPS_PER_CTA + (threadIdx.x >> 5);
    const ulonglong2* xs2 = reinterpret_cast<const ulonglong2*>(xs);

    // this lane's output coordinates within a task: (r = lane&3, b = lane>>2)
    const int lr = lane & 3;
    const int lb = lane >> 2;

    for (int task = gwarp; task < NTASKS; task += TOTAL_WARPS) {
        const int rg    = task >> 2;          // row group
        const int kc    = task & 3;           // K-chunk
        const int n0    = rg * RPW;
        const int kbase = kc * KCH;

        const char* wr = reinterpret_cast<const char*>(
            w + (size_t)n0 * KDIM + kbase);
        const ulonglong2* xb = xs2 + (kbase >> 2);  // x chunk base (16B units)

        ull acc[RPW][BSZ];
        #pragma unroll
        for (int r = 0; r < RPW; r++)
            #pragma unroll
            for (int b = 0; b < BSZ; b++)
                acc[r][b] = 0ULL;

        #pragma unroll 2
        for (int it = 0; it < KITERS; it++) {
            const int koff = (it * 32 + lane) * 16;   // byte offset in chunk

            ull w0l, w0h, w1l, w1h, w2l, w2h, w3l, w3h;
            ldg_cs_v2u64(wr +                 koff, w0l, w0h);
            ldg_cs_v2u64(wr +     KDIM * 4 +  koff, w1l, w1h);
            ldg_cs_v2u64(wr + 2 * KDIM * 4 +  koff, w2l, w2h);
            ldg_cs_v2u64(wr + 3 * KDIM * 4 +  koff, w3l, w3h);

            const int xoff = it * 32 + lane;          // 16B-unit offset
            #pragma unroll
            for (int b = 0; b < BSZ; b++) {
                ulonglong2 xv = xb[b * (KDIM / 4) + xoff];
                ffma2(acc[0][b], w0l, xv.x); ffma2(acc[0][b], w0h, xv.y);
                ffma2(acc[1][b], w1l, xv.x); ffma2(acc[1][b], w1h, xv.y);
                ffma2(acc[2][b], w2l, xv.x); ffma2(acc[2][b], w2h, xv.y);
                ffma2(acc[3][b], w3l, xv.x); ffma2(acc[3][b], w3h, xv.y);
            }
        }

        // ---- butterfly: 32 partials across 32 lanes in 31 SHFL ----
        // v[i] <-> (r = i & 3, b = i >> 2); after 5 rounds lane l holds v[l].
        float v[32];
        #pragma unroll
        for (int b = 0; b < BSZ; b++)
            #pragma unroll
            for (int r = 0; r < RPW; r++)
                v[b * RPW + r] = sum2(acc[r][b]);

        #pragma unroll
        for (int s = 16; s >= 1; s >>= 1) {
            const bool hi = (lane & s) != 0;
            #pragma unroll
            for (int j = 0; j < s; j++) {
                float mine  = hi ? v[j + s] : v[j];
                float sent  = hi ? v[j]     : v[j + s];
                float other = __shfl_xor_sync(0xFFFFFFFFu, sent, s);
                v[j] = mine + other;
            }
        }

        // ---- publish partial, then last-arriving warp combines in place ----
        g_partial[((size_t)kc * BSZ + lb) * NDIM + n0 + lr] = v[0];
        __threadfence();

        int old = 0;
        if (lane == 0)
            old = atomicAdd(&g_cnt[rg], 1);
        old = __shfl_sync(0xFFFFFFFFu, old, 0);

        if (old == SPLITK - 1) {
            // deterministic sum order independent of which kc arrives last:
            // read all 4 published partials (own one included, via L2).
            float p0 = ldg_cg_f32(&g_partial[((size_t)0 * BSZ + lb) * NDIM + n0 + lr]);
            float p1 = ldg_cg_f32(&g_partial[((size_t)1 * BSZ + lb) * NDIM + n0 + lr]);
            float p2 = ldg_cg_f32(&g_partial[((size_t)2 * BSZ + lb) * NDIM + n0 + lr]);
            float p3 = ldg_cg_f32(&g_partial[((size_t)3 * BSZ + lb) * NDIM + n0 + lr]);
            out[(size_t)lb * NDIM + n0 + lr] = (p0 + p1) + (p2 + p3);
            if (lane == 0)
                g_cnt[rg] = 0;   // restore for next graph replay
        }
    }
}

extern "C" void kernel_launch(void* const* d_in, const int* in_sizes, int n_in,
                              void* d_out, int out_size) {
    const float* x = (const float*)d_in[0];
    const float* w = (const float*)d_in[1];
    if (n_in >= 2 && in_sizes[0] == NDIM * KDIM) {   // defensive order fix
        const float* t = x; x = w; w = t;
    }
    float* out = (float*)d_out;

    cudaFuncSetAttribute(asl_gemv_kernel,
                         cudaFuncAttributeMaxDynamicSharedMemorySize,
                         SMEM_BYTES);

    asl_gemv_kernel<<<NCTAS, THREADS, SMEM_BYTES>>>(x, w, out);
}

// round 12
// speedup vs baseline: 1.1395x; 1.1395x over previous
#include <cuda_runtime.h>
#include <cstdint>

// Problem constants
#define BSZ     8
#define KDIM    4096
#define NDIM    11008
#define RPW     4                        // rows per warp task
#define SPLITK  4
#define KCH     (KDIM / SPLITK)          // 1024 floats per K-chunk
#define KITERS  (KCH / 128)              // 8 iterations (128 floats/row/iter)
#define WARPS_PER_CTA 16
#define THREADS (WARPS_PER_CTA * 32)     // 512
#define NCTAS   148
#define TOTAL_WARPS (NCTAS * WARPS_PER_CTA)   // 2368
#define NROWGROUPS (NDIM / RPW)               // 2752
#define NTASKS  (NROWGROUPS * SPLITK)         // 11008
#define SMEM_BYTES (BSZ * KDIM * 4)           // 131072

// Split-K partial sums: [SPLITK][BSZ][NDIM]
__device__ float g_partial[SPLITK * BSZ * NDIM];
// grid-barrier counters (zero at load; restored to 0 every run)
__device__ int g_arrive;
__device__ int g_done;

typedef unsigned long long ull;

// ---- packed f32x2 FMA (Blackwell f32x2 pipe) ----
__device__ __forceinline__ void ffma2(ull& d, ull a, ull b) {
    asm("fma.rn.f32x2 %0, %1, %2, %0;" : "+l"(d) : "l"(a), "l"(b));
}
__device__ __forceinline__ float sum2(ull a) {
    float lo, hi;
    asm("mov.b64 {%0, %1}, %2;" : "=f"(lo), "=f"(hi) : "l"(a));
    return lo + hi;
}
// streaming 128-bit global load as two packed f32x2 words (bypass L1 reuse)
__device__ __forceinline__ void ldg_cs_v2u64(const void* p, ull& a, ull& b) {
    asm("ld.global.cs.v2.u64 {%0, %1}, [%2];"
        : "=l"(a), "=l"(b) : "l"(p));
}
__device__ __forceinline__ int ldg_cg_s32(const int* p) {
    int v;
    asm volatile("ld.global.cg.s32 %0, [%1];" : "=r"(v) : "l"(p));
    return v;
}
__device__ __forceinline__ float4 ldg_cg_f4(const float* p) {
    float4 v;
    asm volatile("ld.global.cg.v4.f32 {%0, %1, %2, %3}, [%4];"
        : "=f"(v.x), "=f"(v.y), "=f"(v.z), "=f"(v.w) : "l"(p));
    return v;
}

extern __shared__ float xs[];   // [BSZ][KDIM] staged activations

__global__ __launch_bounds__(THREADS, 1)
void asl_gemv_kernel(const float* __restrict__ x,
                     const float* __restrict__ w,
                     float* __restrict__ out) {
    // ---- stage x into shared memory (131 KB), once per CTA ----
    {
        const float4* x4  = reinterpret_cast<const float4*>(x);
        float4*       xs4 = reinterpret_cast<float4*>(xs);
        #pragma unroll 8
        for (int i = threadIdx.x; i < BSZ * KDIM / 4; i += THREADS)
            xs4[i] = x4[i];
    }
    __syncthreads();

    const int lane  = threadIdx.x & 31;
    const int gwarp = blockIdx.x * WARPS_PER_CTA + (threadIdx.x >> 5);
    const ulonglong2* xs2 = reinterpret_cast<const ulonglong2*>(xs);

    for (int task = gwarp; task < NTASKS; task += TOTAL_WARPS) {
        const int rg    = task >> 2;          // row group
        const int kc    = task & 3;           // K-chunk
        const int n0    = rg * RPW;
        const int kbase = kc * KCH;

        const char* wr = reinterpret_cast<const char*>(
            w + (size_t)n0 * KDIM + kbase);
        const ulonglong2* xb = xs2 + (kbase >> 2);  // x chunk base (16B units)

        ull acc[RPW][BSZ];
        #pragma unroll
        for (int r = 0; r < RPW; r++)
            #pragma unroll
            for (int b = 0; b < BSZ; b++)
                acc[r][b] = 0ULL;

        #pragma unroll 2
        for (int it = 0; it < KITERS; it++) {
            const int koff = (it * 32 + lane) * 16;   // byte offset in chunk

            ull w0l, w0h, w1l, w1h, w2l, w2h, w3l, w3h;
            ldg_cs_v2u64(wr +                 koff, w0l, w0h);
            ldg_cs_v2u64(wr +     KDIM * 4 +  koff, w1l, w1h);
            ldg_cs_v2u64(wr + 2 * KDIM * 4 +  koff, w2l, w2h);
            ldg_cs_v2u64(wr + 3 * KDIM * 4 +  koff, w3l, w3h);

            const int xoff = it * 32 + lane;          // 16B-unit offset
            #pragma unroll
            for (int b = 0; b < BSZ; b++) {
                ulonglong2 xv = xb[b * (KDIM / 4) + xoff];
                ffma2(acc[0][b], w0l, xv.x); ffma2(acc[0][b], w0h, xv.y);
                ffma2(acc[1][b], w1l, xv.x); ffma2(acc[1][b], w1h, xv.y);
                ffma2(acc[2][b], w2l, xv.x); ffma2(acc[2][b], w2h, xv.y);
                ffma2(acc[3][b], w3l, xv.x); ffma2(acc[3][b], w3h, xv.y);
            }
        }

        // ---- butterfly: 32 partials across 32 lanes in 31 SHFL ----
        float v[32];
        #pragma unroll
        for (int b = 0; b < BSZ; b++)
            #pragma unroll
            for (int r = 0; r < RPW; r++)
                v[b * RPW + r] = sum2(acc[r][b]);

        #pragma unroll
        for (int s = 16; s >= 1; s >>= 1) {
            const bool hi = (lane & s) != 0;
            #pragma unroll
            for (int j = 0; j < s; j++) {
                float mine  = hi ? v[j + s] : v[j];
                float sent  = hi ? v[j]     : v[j + s];
                float other = __shfl_xor_sync(0xFFFFFFFFu, sent, s);
                v[j] = mine + other;
            }
        }

        // lane l -> g_partial[kc][b = l>>2][n0 + (l&3)]  (fire-and-forget)
        g_partial[((size_t)kc * BSZ + (lane >> 2)) * NDIM + n0 + (lane & 3)]
            = v[0];
    }

    // ==== grid barrier: ONE fence + arrive per CTA, then spin ====
    __syncthreads();
    if (threadIdx.x == 0) {
        __threadfence();
        atomicAdd(&g_arrive, 1);
        while (ldg_cg_s32(&g_arrive) < NCTAS)
            __nanosleep(128);
    }
    __syncthreads();

    // ==== cooperative combine: out = sum over SPLITK partials ====
    {
        const int total4 = BSZ * NDIM / 4;                 // 22016
        const int i = blockIdx.x * THREADS + threadIdx.x;  // 75776 threads
        if (i < total4) {
            const float* p = g_partial;
            float4 a0 = ldg_cg_f4(p + (size_t)4 * i);
            float4 a1 = ldg_cg_f4(p + (size_t)4 * (i +     total4));
            float4 a2 = ldg_cg_f4(p + (size_t)4 * (i + 2 * total4));
            float4 a3 = ldg_cg_f4(p + (size_t)4 * (i + 3 * total4));
            float4 o;
            o.x = (a0.x + a1.x) + (a2.x + a3.x);
            o.y = (a0.y + a1.y) + (a2.y + a3.y);
            o.z = (a0.z + a1.z) + (a2.z + a3.z);
            o.w = (a0.w + a1.w) + (a2.w + a3.w);
            reinterpret_cast<float4*>(out)[i] = o;
        }
    }

    // ==== reset counters for next graph replay (last CTA to finish) ====
    __syncthreads();
    if (threadIdx.x == 0) {
        const int old = atomicAdd(&g_done, 1);
        if (old == NCTAS - 1) {
            g_arrive = 0;
            g_done   = 0;
        }
    }
}

extern "C" void kernel_launch(void* const* d_in, const int* in_sizes, int n_in,
                              void* d_out, int out_size) {
    const float* x = (const float*)d_in[0];
    const float* w = (const float*)d_in[1];
    if (n_in >= 2 && in_sizes[0] == NDIM * KDIM) {   // defensive order fix
        const float* t = x; x = w; w = t;
    }
    float* out = (float*)d_out;

    cudaFuncSetAttribute(asl_gemv_kernel,
                         cudaFuncAttributeMaxDynamicSharedMemorySize,
                         SMEM_BYTES);

    asl_gemv_kernel<<<NCTAS, THREADS, SMEM_BYTES>>>(x, w, out);
}

// round 13
// speedup vs baseline: 1.2015x; 1.0544x over previous
#include <cuda_runtime.h>
#include <cstdint>

// Problem constants
#define BSZ     8
#define KDIM    4096
#define NDIM    11008
#define RPW     4                        // rows per warp task
#define SPLITK  4
#define KCH     (KDIM / SPLITK)          // 1024 floats per K-chunk
#define KITERS  (KCH / 128)              // 8 iterations (128 floats/row/iter)
#define WARPS_PER_CTA 16
#define THREADS (WARPS_PER_CTA * 32)     // 512
#define CTAS_PER_KC 37
#define NCTAS   (CTAS_PER_KC * SPLITK)   // 148
#define WARPS_PER_KC (CTAS_PER_KC * WARPS_PER_CTA)   // 592
#define NROWGROUPS (NDIM / RPW)          // 2752
#define SMEM_BYTES (BSZ * KCH * 4)       // 32768

// Split-K partial sums: [SPLITK][BSZ][NDIM]
__device__ float g_partial[SPLITK * BSZ * NDIM];
// grid-barrier counters (zero at load; restored to 0 every run)
__device__ int g_arrive;
__device__ int g_done;

typedef unsigned long long ull;

// ---- packed f32x2 FMA (Blackwell f32x2 pipe) ----
__device__ __forceinline__ void ffma2(ull& d, ull a, ull b) {
    asm("fma.rn.f32x2 %0, %1, %2, %0;" : "+l"(d) : "l"(a), "l"(b));
}
__device__ __forceinline__ float sum2(ull a) {
    float lo, hi;
    asm("mov.b64 {%0, %1}, %2;" : "=f"(lo), "=f"(hi) : "l"(a));
    return lo + hi;
}
// streaming 128-bit global load as two packed f32x2 words (bypass L1 reuse)
__device__ __forceinline__ void ldg_cs_v2u64(const void* p, ull& a, ull& b) {
    asm("ld.global.cs.v2.u64 {%0, %1}, [%2];"
        : "=l"(a), "=l"(b) : "l"(p));
}
__device__ __forceinline__ int ldg_cg_s32(const int* p) {
    int v;
    asm volatile("ld.global.cg.s32 %0, [%1];" : "=r"(v) : "l"(p));
    return v;
}
__device__ __forceinline__ float4 ldg_cg_f4(const float* p) {
    float4 v;
    asm volatile("ld.global.cg.v4.f32 {%0, %1, %2, %3}, [%4];"
        : "=f"(v.x), "=f"(v.y), "=f"(v.z), "=f"(v.w) : "l"(p));
    return v;
}

extern __shared__ float xs[];   // [BSZ][KCH] this CTA's x chunk

__global__ __launch_bounds__(THREADS, 1)
void asl_gemv_kernel(const float* __restrict__ x,
                     const float* __restrict__ w,
                     float* __restrict__ out) {
    const int kc        = blockIdx.x & 3;        // fixed K-chunk per CTA
    const int cta_in_kc = blockIdx.x >> 2;       // 0..36
    const int kbase     = kc * KCH;

    // ---- stage this kc's x chunk (8 x 1024 floats = 32 KB) ----
    {
        const float4* x4  = reinterpret_cast<const float4*>(x);
        float4*       xs4 = reinterpret_cast<float4*>(xs);
        #pragma unroll 4
        for (int i = threadIdx.x; i < BSZ * KCH / 4; i += THREADS) {
            const int b = i >> 8;                // / (KCH/4)
            const int o = i & 255;
            xs4[i] = x4[b * (KDIM / 4) + (kbase >> 2) + o];
        }
    }
    __syncthreads();

    const int lane = threadIdx.x & 31;
    const int wid  = threadIdx.x >> 5;
    const ulonglong2* xs2 = reinterpret_cast<const ulonglong2*>(xs);

    for (int rg = cta_in_kc * WARPS_PER_CTA + wid; rg < NROWGROUPS;
         rg += WARPS_PER_KC) {
        const int n0 = rg * RPW;
        const char* wr = reinterpret_cast<const char*>(
            w + (size_t)n0 * KDIM + kbase);

        ull acc[RPW][BSZ];
        #pragma unroll
        for (int r = 0; r < RPW; r++)
            #pragma unroll
            for (int b = 0; b < BSZ; b++)
                acc[r][b] = 0ULL;

        #pragma unroll 2
        for (int it = 0; it < KITERS; it++) {
            const int koff = (it * 32 + lane) * 16;   // byte offset in chunk

            ull w0l, w0h, w1l, w1h, w2l, w2h, w3l, w3h;
            ldg_cs_v2u64(wr +                 koff, w0l, w0h);
            ldg_cs_v2u64(wr +     KDIM * 4 +  koff, w1l, w1h);
            ldg_cs_v2u64(wr + 2 * KDIM * 4 +  koff, w2l, w2h);
            ldg_cs_v2u64(wr + 3 * KDIM * 4 +  koff, w3l, w3h);

            const int xoff = it * 32 + lane;          // 16B-unit offset
            #pragma unroll
            for (int b = 0; b < BSZ; b++) {
                ulonglong2 xv = xs2[b * (KCH / 4) + xoff];
                ffma2(acc[0][b], w0l, xv.x); ffma2(acc[0][b], w0h, xv.y);
                ffma2(acc[1][b], w1l, xv.x); ffma2(acc[1][b], w1h, xv.y);
                ffma2(acc[2][b], w2l, xv.x); ffma2(acc[2][b], w2h, xv.y);
                ffma2(acc[3][b], w3l, xv.x); ffma2(acc[3][b], w3h, xv.y);
            }
        }

        // ---- butterfly: 32 partials across 32 lanes in 31 SHFL ----
        float v[32];
        #pragma unroll
        for (int b = 0; b < BSZ; b++)
            #pragma unroll
            for (int r = 0; r < RPW; r++)
                v[b * RPW + r] = sum2(acc[r][b]);

        #pragma unroll
        for (int s = 16; s >= 1; s >>= 1) {
            const bool hi = (lane & s) != 0;
            #pragma unroll
            for (int j = 0; j < s; j++) {
                float mine  = hi ? v[j + s] : v[j];
                float sent  = hi ? v[j]     : v[j + s];
                float other = __shfl_xor_sync(0xFFFFFFFFu, sent, s);
                v[j] = mine + other;
            }
        }

        // lane l -> g_partial[kc][b = l>>2][n0 + (l&3)]  (fire-and-forget)
        g_partial[((size_t)kc * BSZ + (lane >> 2)) * NDIM + n0 + (lane & 3)]
            = v[0];
    }

    // ==== grid barrier: ONE fence + arrive per CTA, then spin ====
    __syncthreads();
    if (threadIdx.x == 0) {
        __threadfence();
        atomicAdd(&g_arrive, 1);
        while (ldg_cg_s32(&g_arrive) < NCTAS)
            __nanosleep(128);
    }
    __syncthreads();

    // ==== cooperative combine: out = sum over SPLITK partials ====
    {
        const int total4 = BSZ * NDIM / 4;                 // 22016
        const int i = blockIdx.x * THREADS + threadIdx.x;  // 75776 threads
        if (i < total4) {
            const float* p = g_partial;
            float4 a0 = ldg_cg_f4(p + (size_t)4 * i);
            float4 a1 = ldg_cg_f4(p + (size_t)4 * (i +     total4));
            float4 a2 = ldg_cg_f4(p + (size_t)4 * (i + 2 * total4));
            float4 a3 = ldg_cg_f4(p + (size_t)4 * (i + 3 * total4));
            float4 o;
            o.x = (a0.x + a1.x) + (a2.x + a3.x);
            o.y = (a0.y + a1.y) + (a2.y + a3.y);
            o.z = (a0.z + a1.z) + (a2.z + a3.z);
            o.w = (a0.w + a1.w) + (a2.w + a3.w);
            reinterpret_cast<float4*>(out)[i] = o;
        }
    }

    // ==== reset counters for next graph replay (last CTA to finish) ====
    __syncthreads();
    if (threadIdx.x == 0) {
        const int old = atomicAdd(&g_done, 1);
        if (old == NCTAS - 1) {
            g_arrive = 0;
            g_done   = 0;
        }
    }
}

extern "C" void kernel_launch(void* const* d_in, const int* in_sizes, int n_in,
                              void* d_out, int out_size) {
    const float* x = (const float*)d_in[0];
    const float* w = (const float*)d_in[1];
    if (n_in >= 2 && in_sizes[0] == NDIM * KDIM) {   // defensive order fix
        const float* t = x; x = w; w = t;
    }
    float* out = (float*)d_out;

    cudaFuncSetAttribute(asl_gemv_kernel,
                         cudaFuncAttributeMaxDynamicSharedMemorySize,
                         SMEM_BYTES);

    asl_gemv_kernel<<<NCTAS, THREADS, SMEM_BYTES>>>(x, w, out);
}